// round 2
// baseline (speedup 1.0000x reference)
#include <cuda_runtime.h>
#include <math.h>
#include <stdint.h>

#define SLEN 4096
#define DMODEL 1024
#define NHEAD 16
#define HDIM 64

// scratch (allocation-free rule: __device__ globals)
__device__ float g_q[SLEN * DMODEL];
__device__ float g_k[SLEN * DMODEL];
__device__ float g_v[SLEN * DMODEL];
__device__ float g_attn[SLEN * DMODEL];

// ---------------------------------------------------------------------------
// helpers: tf32 split + mma
// ---------------------------------------------------------------------------
__device__ __forceinline__ uint32_t f2tf32(float x) {
    uint32_t r;
    asm("cvt.rna.tf32.f32 %0, %1;" : "=r"(r) : "f"(x));
    return r;
}

__device__ __forceinline__ void mma_tf32(
    float c[4], uint32_t a0, uint32_t a1, uint32_t a2, uint32_t a3,
    uint32_t b0, uint32_t b1)
{
    asm volatile(
        "mma.sync.aligned.m16n8k8.row.col.f32.tf32.tf32.f32 "
        "{%0,%1,%2,%3},{%4,%5,%6,%7},{%8,%9},{%0,%1,%2,%3};\n"
        : "+f"(c[0]), "+f"(c[1]), "+f"(c[2]), "+f"(c[3])
        : "r"(a0), "r"(a1), "r"(a2), "r"(a3), "r"(b0), "r"(b1));
}

// ---------------------------------------------------------------------------
// C[M][N] = A[M][K] @ B[N][K]^T + bias[N]  via 3xTF32 mma (fp32 accuracy)
// BM=BN=128, BK=16, 256 threads (8 warps as 2x4), warp tile 64x32.
// ---------------------------------------------------------------------------
#define BM 128
#define BN 128
#define BKK 16
#define KPAD 4
#define KLD (BKK + KPAD)

__global__ __launch_bounds__(256) void gemm_tf32_nt(
    const float* __restrict__ A, const float* __restrict__ B,
    const float* __restrict__ bias, float* __restrict__ C,
    int M, int N, int K)
{
    __shared__ uint32_t AsHi[BM][KLD];
    __shared__ uint32_t AsLo[BM][KLD];
    __shared__ uint32_t BsHi[BN][KLD];
    __shared__ uint32_t BsLo[BN][KLD];

    const int tid  = threadIdx.x;
    const int warp = tid >> 5;
    const int lane = tid & 31;
    const int wm = warp >> 2;          // 0..1
    const int wn = warp & 3;           // 0..3
    const int lr = lane >> 2;          // 0..7
    const int lc = lane & 3;           // 0..3
    const int brow = blockIdx.y * BM;
    const int bcol = blockIdx.x * BN;

    float acc[4][4][4];                // [mtile][ntile][frag]
#pragma unroll
    for (int i = 0; i < 4; i++)
#pragma unroll
        for (int j = 0; j < 4; j++)
#pragma unroll
            for (int f = 0; f < 4; f++) acc[i][j][f] = 0.f;

    for (int k0 = 0; k0 < K; k0 += BKK) {
        // ---- load + split tiles into smem (hi/lo tf32) ----
#pragma unroll
        for (int it = 0; it < 2; it++) {
            int f   = tid + it * 256;       // 0..511
            int row = f >> 2;               // 0..127
            int kq  = (f & 3) * 4;          // 0,4,8,12
            float4 a4 = *(const float4*)&A[(size_t)(brow + row) * K + k0 + kq];
            float4 b4 = *(const float4*)&B[(size_t)(bcol + row) * K + k0 + kq];
            uint32_t h, l;
            float av[4] = {a4.x, a4.y, a4.z, a4.w};
            float bv[4] = {b4.x, b4.y, b4.z, b4.w};
#pragma unroll
            for (int e = 0; e < 4; e++) {
                h = f2tf32(av[e]);
                l = f2tf32(av[e] - __uint_as_float(h));
                AsHi[row][kq + e] = h; AsLo[row][kq + e] = l;
                h = f2tf32(bv[e]);
                l = f2tf32(bv[e] - __uint_as_float(h));
                BsHi[row][kq + e] = h; BsLo[row][kq + e] = l;
            }
        }
        __syncthreads();

        // ---- compute: 2 k8 steps ----
#pragma unroll
        for (int kk = 0; kk < BKK; kk += 8) {
            uint32_t ahi[4][4], alo[4][4];
#pragma unroll
            for (int mt = 0; mt < 4; mt++) {
                int r = wm * 64 + mt * 16 + lr;
                ahi[mt][0] = AsHi[r    ][kk + lc];
                ahi[mt][1] = AsHi[r + 8][kk + lc];
                ahi[mt][2] = AsHi[r    ][kk + lc + 4];
                ahi[mt][3] = AsHi[r + 8][kk + lc + 4];
                alo[mt][0] = AsLo[r    ][kk + lc];
                alo[mt][1] = AsLo[r + 8][kk + lc];
                alo[mt][2] = AsLo[r    ][kk + lc + 4];
                alo[mt][3] = AsLo[r + 8][kk + lc + 4];
            }
#pragma unroll
            for (int nt = 0; nt < 4; nt++) {
                int c = wn * 32 + nt * 8 + lr;
                uint32_t bh0 = BsHi[c][kk + lc], bh1 = BsHi[c][kk + lc + 4];
                uint32_t bl0 = BsLo[c][kk + lc], bl1 = BsLo[c][kk + lc + 4];
#pragma unroll
                for (int mt = 0; mt < 4; mt++) {
                    // hi*hi + hi*lo + lo*hi  (3xTF32)
                    mma_tf32(acc[mt][nt], ahi[mt][0], ahi[mt][1], ahi[mt][2], ahi[mt][3], bh0, bh1);
                    mma_tf32(acc[mt][nt], ahi[mt][0], ahi[mt][1], ahi[mt][2], ahi[mt][3], bl0, bl1);
                    mma_tf32(acc[mt][nt], alo[mt][0], alo[mt][1], alo[mt][2], alo[mt][3], bh0, bh1);
                }
            }
        }
        __syncthreads();
    }

    // ---- epilogue ----
#pragma unroll
    for (int mt = 0; mt < 4; mt++) {
        int r0 = brow + wm * 64 + mt * 16 + lr;
#pragma unroll
        for (int nt = 0; nt < 4; nt++) {
            int col = bcol + wn * 32 + nt * 8 + 2 * lc;
            float b0 = bias ? bias[col]     : 0.f;
            float b1 = bias ? bias[col + 1] : 0.f;
            float2 w0 = make_float2(acc[mt][nt][0] + b0, acc[mt][nt][1] + b1);
            float2 w1 = make_float2(acc[mt][nt][2] + b0, acc[mt][nt][3] + b1);
            *(float2*)&C[(size_t)r0 * N + col]       = w0;
            *(float2*)&C[(size_t)(r0 + 8) * N + col] = w1;
        }
    }
}

// ---------------------------------------------------------------------------
// Causal flash attention with ALiBi key-position bias (fp32, unchanged).
// ---------------------------------------------------------------------------
#define BQ 64
#define BT 32

__global__ __launch_bounds__(256) void flash_attn(
    const float* __restrict__ Q, const float* __restrict__ K,
    const float* __restrict__ V, float* __restrict__ O)
{
    const int h  = blockIdx.y;
    const int qt = gridDim.x - 1 - blockIdx.x;
    const int q0 = qt * BQ;
    const float slope = exp2f(-0.5f * (float)(h + 1));

    __shared__ float QsT[HDIM][BQ + 1];
    __shared__ float KsT[HDIM][BT + 1];
    __shared__ float Vs [BT][HDIM];
    __shared__ float PsT[BT][BQ + 1];

    const int tid = threadIdx.x;
    const int tr  = (tid >> 4) * 4;
    const int cg  = tid & 15;

    for (int f = tid; f < BQ * 16; f += 256) {
        int r = f >> 4, d4 = (f & 15) * 4;
        float4 v4 = *(const float4*)&Q[(size_t)(q0 + r) * DMODEL + h * HDIM + d4];
        QsT[d4 + 0][r] = v4.x; QsT[d4 + 1][r] = v4.y;
        QsT[d4 + 2][r] = v4.z; QsT[d4 + 3][r] = v4.w;
    }

    float m[4], l[4], o[4][4];
#pragma unroll
    for (int i = 0; i < 4; i++) {
        m[i] = -INFINITY; l[i] = 0.f;
#pragma unroll
        for (int j = 0; j < 4; j++) o[i][j] = 0.f;
    }

    const int ntiles = 2 * (qt + 1);
    for (int t = 0; t < ntiles; t++) {
        const int t0 = t * BT;
        __syncthreads();

        for (int f = tid; f < BT * 16; f += 256) {
            int r = f >> 4, d4 = (f & 15) * 4;
            float4 kv = *(const float4*)&K[(size_t)(t0 + r) * DMODEL + h * HDIM + d4];
            KsT[d4 + 0][r] = kv.x; KsT[d4 + 1][r] = kv.y;
            KsT[d4 + 2][r] = kv.z; KsT[d4 + 3][r] = kv.w;
            float4 vv = *(const float4*)&V[(size_t)(t0 + r) * DMODEL + h * HDIM + d4];
            *(float4*)&Vs[r][d4] = vv;
        }
        __syncthreads();

        float s[4][2];
#pragma unroll
        for (int i = 0; i < 4; i++) { s[i][0] = 0.f; s[i][1] = 0.f; }
#pragma unroll 8
        for (int d = 0; d < HDIM; d++) {
            float a0 = QsT[d][tr + 0], a1 = QsT[d][tr + 1];
            float a2 = QsT[d][tr + 2], a3 = QsT[d][tr + 3];
            float b0 = KsT[d][cg], b1 = KsT[d][cg + 16];
            s[0][0] += a0 * b0; s[0][1] += a0 * b1;
            s[1][0] += a1 * b0; s[1][1] += a1 * b1;
            s[2][0] += a2 * b0; s[2][1] += a2 * b1;
            s[3][0] += a3 * b0; s[3][1] += a3 * b1;
        }

#pragma unroll
        for (int i = 0; i < 4; i++) {
            int row = q0 + tr + i;
#pragma unroll
            for (int j = 0; j < 2; j++) {
                int col = t0 + cg + 16 * j;
                float val = s[i][j] * 0.125f - slope * (float)col;
                s[i][j] = (col <= row) ? val : -INFINITY;
            }
        }

#pragma unroll
        for (int i = 0; i < 4; i++) {
            float v = fmaxf(s[i][0], s[i][1]);
            v = fmaxf(v, __shfl_xor_sync(0xffffffffu, v, 1));
            v = fmaxf(v, __shfl_xor_sync(0xffffffffu, v, 2));
            v = fmaxf(v, __shfl_xor_sync(0xffffffffu, v, 4));
            v = fmaxf(v, __shfl_xor_sync(0xffffffffu, v, 8));
            float mn = fmaxf(m[i], v);
            float sc = __expf(m[i] - mn);
            m[i] = mn;
            l[i] *= sc;
#pragma unroll
            for (int j = 0; j < 4; j++) o[i][j] *= sc;
            float p0 = __expf(s[i][0] - mn);
            float p1 = __expf(s[i][1] - mn);
            s[i][0] = p0; s[i][1] = p1;
            float rs = p0 + p1;
            rs += __shfl_xor_sync(0xffffffffu, rs, 1);
            rs += __shfl_xor_sync(0xffffffffu, rs, 2);
            rs += __shfl_xor_sync(0xffffffffu, rs, 4);
            rs += __shfl_xor_sync(0xffffffffu, rs, 8);
            l[i] += rs;
        }

#pragma unroll
        for (int i = 0; i < 4; i++) {
            PsT[cg     ][tr + i] = s[i][0];
            PsT[cg + 16][tr + i] = s[i][1];
        }
        __syncthreads();

#pragma unroll 4
        for (int tt = 0; tt < BT; tt++) {
            float p0 = PsT[tt][tr + 0], p1 = PsT[tt][tr + 1];
            float p2 = PsT[tt][tr + 2], p3 = PsT[tt][tr + 3];
            float v0 = Vs[tt][cg], v1 = Vs[tt][cg + 16];
            float v2 = Vs[tt][cg + 32], v3 = Vs[tt][cg + 48];
            o[0][0] += p0 * v0; o[0][1] += p0 * v1; o[0][2] += p0 * v2; o[0][3] += p0 * v3;
            o[1][0] += p1 * v0; o[1][1] += p1 * v1; o[1][2] += p1 * v2; o[1][3] += p1 * v3;
            o[2][0] += p2 * v0; o[2][1] += p2 * v1; o[2][2] += p2 * v2; o[2][3] += p2 * v3;
            o[3][0] += p3 * v0; o[3][1] += p3 * v1; o[3][2] += p3 * v2; o[3][3] += p3 * v3;
        }
    }

#pragma unroll
    for (int i = 0; i < 4; i++) {
        float inv = 1.f / l[i];
#pragma unroll
        for (int j = 0; j < 4; j++)
            O[(size_t)(q0 + tr + i) * DMODEL + h * HDIM + cg + 16 * j] = o[i][j] * inv;
    }
}

// ---------------------------------------------------------------------------
extern "C" void kernel_launch(void* const* d_in, const int* in_sizes, int n_in,
                              void* d_out, int out_size)
{
    const float* x  = (const float*)d_in[0];
    const float* Wq = (const float*)d_in[1];
    const float* bq = (const float*)d_in[2];
    const float* Wk = (const float*)d_in[3];
    const float* Wv = (const float*)d_in[4];
    const float* bv = (const float*)d_in[5];
    const float* Wo = (const float*)d_in[6];
    float* out = (float*)d_out;

    float *qp, *kp, *vp, *ap;
    cudaGetSymbolAddress((void**)&qp, g_q);
    cudaGetSymbolAddress((void**)&kp, g_k);
    cudaGetSymbolAddress((void**)&vp, g_v);
    cudaGetSymbolAddress((void**)&ap, g_attn);

    dim3 ggrid(DMODEL / BN, SLEN / BM);     // (8, 32)
    gemm_tf32_nt<<<ggrid, 256>>>(x, Wq, bq, qp, SLEN, DMODEL, DMODEL);
    gemm_tf32_nt<<<ggrid, 256>>>(x, Wk, nullptr, kp, SLEN, DMODEL, DMODEL);
    gemm_tf32_nt<<<ggrid, 256>>>(x, Wv, bv, vp, SLEN, DMODEL, DMODEL);

    dim3 agrid(SLEN / BQ, NHEAD);           // (64, 16)
    flash_attn<<<agrid, 256>>>(qp, kp, vp, ap);

    gemm_tf32_nt<<<ggrid, 256>>>(ap, Wo, nullptr, out, SLEN, DMODEL, DMODEL);
}

// round 6
// speedup vs baseline: 1.4851x; 1.4851x over previous
#include <cuda_runtime.h>
#include <cuda_fp16.h>
#include <math.h>
#include <stdint.h>

#define SLEN 4096
#define DMODEL 1024
#define NHEAD 16
#define HDIM 64

// scratch (allocation-free rule: __device__ globals)
__device__ float g_q[SLEN * DMODEL];
__device__ float g_k[SLEN * DMODEL];
__device__ float g_v[SLEN * DMODEL];
__device__ float g_attn[SLEN * DMODEL];

// ---------------------------------------------------------------------------
// helpers
// ---------------------------------------------------------------------------
__device__ __forceinline__ uint32_t f2tf32(float x) {
    uint32_t r;
    asm("cvt.rna.tf32.f32 %0, %1;" : "=r"(r) : "f"(x));
    return r;
}
__device__ __forceinline__ float tf32res(float x, uint32_t hi) {
    uint32_t r = f2tf32(x - __uint_as_float(hi));
    return __uint_as_float(r);
}

__device__ __forceinline__ void mma_tf32(
    float c[4], uint32_t a0, uint32_t a1, uint32_t a2, uint32_t a3,
    uint32_t b0, uint32_t b1)
{
    asm volatile(
        "mma.sync.aligned.m16n8k8.row.col.f32.tf32.tf32.f32 "
        "{%0,%1,%2,%3},{%4,%5,%6,%7},{%8,%9},{%0,%1,%2,%3};\n"
        : "+f"(c[0]), "+f"(c[1]), "+f"(c[2]), "+f"(c[3])
        : "r"(a0), "r"(a1), "r"(a2), "r"(a3), "r"(b0), "r"(b1));
}

__device__ __forceinline__ void mma_f16(
    float c[4], uint32_t a0, uint32_t a1, uint32_t a2, uint32_t a3,
    uint32_t b0, uint32_t b1)
{
    asm volatile(
        "mma.sync.aligned.m16n8k16.row.col.f32.f16.f16.f32 "
        "{%0,%1,%2,%3},{%4,%5,%6,%7},{%8,%9},{%0,%1,%2,%3};\n"
        : "+f"(c[0]), "+f"(c[1]), "+f"(c[2]), "+f"(c[3])
        : "r"(a0), "r"(a1), "r"(a2), "r"(a3), "r"(b0), "r"(b1));
}

// ---------------------------------------------------------------------------
// C[M][N] = A[M][K] @ B[N][K]^T + bias[N]  via 3xTF32 mma
// ---------------------------------------------------------------------------
#define BM 128
#define BN 128
#define BKK 16
#define KLD (BKK + 4)

__global__ __launch_bounds__(256) void gemm_tf32_nt(
    const float* __restrict__ A, const float* __restrict__ B,
    const float* __restrict__ bias, float* __restrict__ C,
    int M, int N, int K)
{
    __shared__ uint32_t AsHi[BM][KLD];
    __shared__ uint32_t AsLo[BM][KLD];
    __shared__ uint32_t BsHi[BN][KLD];
    __shared__ uint32_t BsLo[BN][KLD];

    const int tid  = threadIdx.x;
    const int warp = tid >> 5;
    const int lane = tid & 31;
    const int wm = warp >> 2;
    const int wn = warp & 3;
    const int lr = lane >> 2;
    const int lc = lane & 3;
    const int brow = blockIdx.y * BM;
    const int bcol = blockIdx.x * BN;

    float acc[4][4][4];
#pragma unroll
    for (int i = 0; i < 4; i++)
#pragma unroll
        for (int j = 0; j < 4; j++)
#pragma unroll
            for (int f = 0; f < 4; f++) acc[i][j][f] = 0.f;

    for (int k0 = 0; k0 < K; k0 += BKK) {
#pragma unroll
        for (int it = 0; it < 2; it++) {
            int f   = tid + it * 256;
            int row = f >> 2;
            int kq  = (f & 3) * 4;
            float4 a4 = *(const float4*)&A[(size_t)(brow + row) * K + k0 + kq];
            float4 b4 = *(const float4*)&B[(size_t)(bcol + row) * K + k0 + kq];
            float av[4] = {a4.x, a4.y, a4.z, a4.w};
            float bv[4] = {b4.x, b4.y, b4.z, b4.w};
#pragma unroll
            for (int e = 0; e < 4; e++) {
                uint32_t h = f2tf32(av[e]);
                AsHi[row][kq + e] = h;
                AsLo[row][kq + e] = f2tf32(av[e] - __uint_as_float(h));
                h = f2tf32(bv[e]);
                BsHi[row][kq + e] = h;
                BsLo[row][kq + e] = f2tf32(bv[e] - __uint_as_float(h));
            }
        }
        __syncthreads();

#pragma unroll
        for (int kk = 0; kk < BKK; kk += 8) {
            uint32_t ahi[4][4], alo[4][4];
#pragma unroll
            for (int mt = 0; mt < 4; mt++) {
                int r = wm * 64 + mt * 16 + lr;
                ahi[mt][0] = AsHi[r    ][kk + lc];
                ahi[mt][1] = AsHi[r + 8][kk + lc];
                ahi[mt][2] = AsHi[r    ][kk + lc + 4];
                ahi[mt][3] = AsHi[r + 8][kk + lc + 4];
                alo[mt][0] = AsLo[r    ][kk + lc];
                alo[mt][1] = AsLo[r + 8][kk + lc];
                alo[mt][2] = AsLo[r    ][kk + lc + 4];
                alo[mt][3] = AsLo[r + 8][kk + lc + 4];
            }
#pragma unroll
            for (int nt = 0; nt < 4; nt++) {
                int c = wn * 32 + nt * 8 + lr;
                uint32_t bh0 = BsHi[c][kk + lc], bh1 = BsHi[c][kk + lc + 4];
                uint32_t bl0 = BsLo[c][kk + lc], bl1 = BsLo[c][kk + lc + 4];
#pragma unroll
                for (int mt = 0; mt < 4; mt++) {
                    mma_tf32(acc[mt][nt], ahi[mt][0], ahi[mt][1], ahi[mt][2], ahi[mt][3], bh0, bh1);
                    mma_tf32(acc[mt][nt], ahi[mt][0], ahi[mt][1], ahi[mt][2], ahi[mt][3], bl0, bl1);
                    mma_tf32(acc[mt][nt], alo[mt][0], alo[mt][1], alo[mt][2], alo[mt][3], bh0, bh1);
                }
            }
        }
        __syncthreads();
    }

#pragma unroll
    for (int mt = 0; mt < 4; mt++) {
        int r0 = brow + wm * 64 + mt * 16 + lr;
#pragma unroll
        for (int nt = 0; nt < 4; nt++) {
            int col = bcol + wn * 32 + nt * 8 + 2 * lc;
            float b0 = bias ? bias[col]     : 0.f;
            float b1 = bias ? bias[col + 1] : 0.f;
            float2 w0 = make_float2(acc[mt][nt][0] + b0, acc[mt][nt][1] + b1);
            float2 w1 = make_float2(acc[mt][nt][2] + b0, acc[mt][nt][3] + b1);
            *(float2*)&C[(size_t)r0 * N + col]       = w0;
            *(float2*)&C[(size_t)(r0 + 8) * N + col] = w1;
        }
    }
}

// ---------------------------------------------------------------------------
// Tensor-core causal flash attention with ALiBi.
// BQ=64 = 4 warps x m16, 128 THREADS. BT=32.
// S via 3xTF32 mma, PV via fp16 mma (register pass-through for P).
// ---------------------------------------------------------------------------
#define BQ 64
#define BT 32
#define KPADA 4
#define ATHREADS 128

__global__ __launch_bounds__(ATHREADS) void flash_attn_mma(
    const float* __restrict__ Q, const float* __restrict__ K,
    const float* __restrict__ V, float* __restrict__ O)
{
    const int h  = blockIdx.y;
    const int qt = gridDim.x - 1 - blockIdx.x;   // longest first
    const int q0 = qt * BQ;

    const int tid  = threadIdx.x;
    const int warp = tid >> 5;    // 0..3
    const int lane = tid & 31;
    const int lr   = lane >> 2;   // groupID 0..7
    const int qd   = lane & 3;    // threadID in group
    const int R    = warp * 16;   // warp row base (0..48)

    __shared__ float  KsHi[BT][HDIM + KPADA];
    __shared__ float  KsLo[BT][HDIM + KPADA];
    __shared__ __half VsT [HDIM][BT + 8];        // [d][t]
    __shared__ float  QsLo[BQ][HDIM + KPADA];    // staging, then residual

    const float LOG2E = 1.4426950408889634f;
    const float sc2 = 0.125f * LOG2E;
    const float sl2 = exp2f(-0.5f * (float)(h + 1)) * LOG2E;

    // ---- stage Q tile into smem (fp32, coalesced) ----
    for (int f = tid; f < BQ * 16; f += ATHREADS) {
        int r  = f >> 4;
        int c4 = (f & 15) * 4;
        float4 v4 = *(const float4*)&Q[(size_t)(q0 + r) * DMODEL + h * HDIM + c4];
        *(float4*)&QsLo[r][c4] = v4;
    }
    __syncthreads();

    // ---- extract Q hi frags to regs; overwrite smem with tf32 residual ----
    uint32_t qh[8][4];
#pragma unroll
    for (int kt = 0; kt < 8; kt++) {
        int d0 = kt * 8 + qd;
        int r0 = R + lr, r1 = R + lr + 8;
        float v;
        v = QsLo[r0][d0];     qh[kt][0] = f2tf32(v); QsLo[r0][d0]     = tf32res(v, qh[kt][0]);
        v = QsLo[r1][d0];     qh[kt][1] = f2tf32(v); QsLo[r1][d0]     = tf32res(v, qh[kt][1]);
        v = QsLo[r0][d0 + 4]; qh[kt][2] = f2tf32(v); QsLo[r0][d0 + 4] = tf32res(v, qh[kt][2]);
        v = QsLo[r1][d0 + 4]; qh[kt][3] = f2tf32(v); QsLo[r1][d0 + 4] = tf32res(v, qh[kt][3]);
    }

    float oacc[8][4];
#pragma unroll
    for (int i = 0; i < 8; i++)
#pragma unroll
        for (int j = 0; j < 4; j++) oacc[i][j] = 0.f;
    float m0 = -INFINITY, m1 = -INFINITY, l0 = 0.f, l1 = 0.f;

    const int gr0 = q0 + R + lr;
    const int gr1 = gr0 + 8;

    const int ntiles = 2 * (qt + 1);
    for (int t = 0; t < ntiles; t++) {
        const int t0 = t * BT;
        __syncthreads();

        // ---- load K tile, split hi/lo tf32 ----
        for (int f = tid; f < BT * 16; f += ATHREADS) {
            int tk = f >> 4;
            int dg = (f & 15) * 4;
            float4 k4 = *(const float4*)&K[(size_t)(t0 + tk) * DMODEL + h * HDIM + dg];
            float kv[4] = {k4.x, k4.y, k4.z, k4.w};
#pragma unroll
            for (int e = 0; e < 4; e++) {
                uint32_t hi = f2tf32(kv[e]);
                KsHi[tk][dg + e] = __uint_as_float(hi);
                KsLo[tk][dg + e] = tf32res(kv[e], hi);
            }
        }
        // ---- load V transposed as half2 ----
        for (int f = tid; f < HDIM * (BT / 2); f += ATHREADS) {
            int dv = f & 63;            // head-dim col (coalesced across threads)
            int tp = f >> 6;            // time pair 0..15
            const float* vp = &V[(size_t)(t0 + 2 * tp) * DMODEL + h * HDIM + dv];
            float va = vp[0];
            float vb = vp[DMODEL];
            *(__half2*)&VsT[dv][2 * tp] = __floats2half2_rn(va, vb);
        }
        __syncthreads();

        // ---- S = Q K^T (3xTF32) ----
        float sa[4][4];
#pragma unroll
        for (int nt = 0; nt < 4; nt++)
#pragma unroll
            for (int f = 0; f < 4; f++) sa[nt][f] = 0.f;

#pragma unroll
        for (int kt = 0; kt < 8; kt++) {
            int d0 = kt * 8 + qd;
            uint32_t ql0 = __float_as_uint(QsLo[R + lr    ][d0]);
            uint32_t ql1 = __float_as_uint(QsLo[R + lr + 8][d0]);
            uint32_t ql2 = __float_as_uint(QsLo[R + lr    ][d0 + 4]);
            uint32_t ql3 = __float_as_uint(QsLo[R + lr + 8][d0 + 4]);
#pragma unroll
            for (int nt = 0; nt < 4; nt++) {
                int tr_ = nt * 8 + lr;
                uint32_t bh0 = __float_as_uint(KsHi[tr_][d0]);
                uint32_t bh1 = __float_as_uint(KsHi[tr_][d0 + 4]);
                uint32_t bl0 = __float_as_uint(KsLo[tr_][d0]);
                uint32_t bl1 = __float_as_uint(KsLo[tr_][d0 + 4]);
                mma_tf32(sa[nt], qh[kt][0], qh[kt][1], qh[kt][2], qh[kt][3], bh0, bh1);
                mma_tf32(sa[nt], qh[kt][0], qh[kt][1], qh[kt][2], qh[kt][3], bl0, bl1);
                mma_tf32(sa[nt], ql0, ql1, ql2, ql3, bh0, bh1);
            }
        }

        // ---- bias + mask + online softmax (base-2) ----
        float sv[4][4];
        float mx0 = -INFINITY, mx1 = -INFINITY;
#pragma unroll
        for (int nt = 0; nt < 4; nt++) {
            int c = t0 + nt * 8 + 2 * qd;
            float x00 = sa[nt][0] * sc2 - sl2 * (float)c;
            float x01 = sa[nt][1] * sc2 - sl2 * (float)(c + 1);
            float x10 = sa[nt][2] * sc2 - sl2 * (float)c;
            float x11 = sa[nt][3] * sc2 - sl2 * (float)(c + 1);
            if (c     > gr0) x00 = -INFINITY;
            if (c + 1 > gr0) x01 = -INFINITY;
            if (c     > gr1) x10 = -INFINITY;
            if (c + 1 > gr1) x11 = -INFINITY;
            sv[nt][0] = x00; sv[nt][1] = x01; sv[nt][2] = x10; sv[nt][3] = x11;
            mx0 = fmaxf(mx0, fmaxf(x00, x01));
            mx1 = fmaxf(mx1, fmaxf(x10, x11));
        }
        mx0 = fmaxf(mx0, __shfl_xor_sync(0xffffffffu, mx0, 1));
        mx0 = fmaxf(mx0, __shfl_xor_sync(0xffffffffu, mx0, 2));
        mx1 = fmaxf(mx1, __shfl_xor_sync(0xffffffffu, mx1, 1));
        mx1 = fmaxf(mx1, __shfl_xor_sync(0xffffffffu, mx1, 2));

        float nm0 = fmaxf(m0, mx0), nm1 = fmaxf(m1, mx1);
        float s0 = exp2f(m0 - nm0), s1 = exp2f(m1 - nm1);
        m0 = nm0; m1 = nm1;

        float rs0 = 0.f, rs1 = 0.f;
        uint32_t pa[2][4];
#pragma unroll
        for (int nt = 0; nt < 4; nt++) {
            float p00 = exp2f(sv[nt][0] - m0);
            float p01 = exp2f(sv[nt][1] - m0);
            float p10 = exp2f(sv[nt][2] - m1);
            float p11 = exp2f(sv[nt][3] - m1);
            rs0 += p00 + p01;
            rs1 += p10 + p11;
            __half2 h0 = __floats2half2_rn(p00, p01);
            __half2 h1 = __floats2half2_rn(p10, p11);
            pa[nt >> 1][(nt & 1) * 2 + 0] = *(uint32_t*)&h0;
            pa[nt >> 1][(nt & 1) * 2 + 1] = *(uint32_t*)&h1;
        }
        rs0 += __shfl_xor_sync(0xffffffffu, rs0, 1);
        rs0 += __shfl_xor_sync(0xffffffffu, rs0, 2);
        rs1 += __shfl_xor_sync(0xffffffffu, rs1, 1);
        rs1 += __shfl_xor_sync(0xffffffffu, rs1, 2);
        l0 = l0 * s0 + rs0;
        l1 = l1 * s1 + rs1;

        // ---- rescale O, then O += P V (fp16 mma) ----
#pragma unroll
        for (int ntO = 0; ntO < 8; ntO++) {
            oacc[ntO][0] *= s0; oacc[ntO][1] *= s0;
            oacc[ntO][2] *= s1; oacc[ntO][3] *= s1;
        }
#pragma unroll
        for (int ktp = 0; ktp < 2; ktp++) {
#pragma unroll
            for (int ntO = 0; ntO < 8; ntO++) {
                int dcol = ntO * 8 + lr;
                uint32_t b0 = *(const uint32_t*)&VsT[dcol][ktp * 16 + 2 * qd];
                uint32_t b1 = *(const uint32_t*)&VsT[dcol][ktp * 16 + 2 * qd + 8];
                mma_f16(oacc[ntO], pa[ktp][0], pa[ktp][1], pa[ktp][2], pa[ktp][3], b0, b1);
            }
        }
    }

    // ---- epilogue ----
    float inv0 = 1.f / l0, inv1 = 1.f / l1;
#pragma unroll
    for (int ntO = 0; ntO < 8; ntO++) {
        int col = h * HDIM + ntO * 8 + 2 * qd;
        float2 w0 = make_float2(oacc[ntO][0] * inv0, oacc[ntO][1] * inv0);
        float2 w1 = make_float2(oacc[ntO][2] * inv1, oacc[ntO][3] * inv1);
        *(float2*)&O[(size_t)gr0 * DMODEL + col] = w0;
        *(float2*)&O[(size_t)gr1 * DMODEL + col] = w1;
    }
}

// ---------------------------------------------------------------------------
extern "C" void kernel_launch(void* const* d_in, const int* in_sizes, int n_in,
                              void* d_out, int out_size)
{
    const float* x  = (const float*)d_in[0];
    const float* Wq = (const float*)d_in[1];
    const float* bq = (const float*)d_in[2];
    const float* Wk = (const float*)d_in[3];
    const float* Wv = (const float*)d_in[4];
    const float* bv = (const float*)d_in[5];
    const float* Wo = (const float*)d_in[6];
    float* out = (float*)d_out;

    float *qp, *kp, *vp, *ap;
    cudaGetSymbolAddress((void**)&qp, g_q);
    cudaGetSymbolAddress((void**)&kp, g_k);
    cudaGetSymbolAddress((void**)&vp, g_v);
    cudaGetSymbolAddress((void**)&ap, g_attn);

    dim3 ggrid(DMODEL / BN, SLEN / BM);
    gemm_tf32_nt<<<ggrid, 256>>>(x, Wq, bq, qp, SLEN, DMODEL, DMODEL);
    gemm_tf32_nt<<<ggrid, 256>>>(x, Wk, nullptr, kp, SLEN, DMODEL, DMODEL);
    gemm_tf32_nt<<<ggrid, 256>>>(x, Wv, bv, vp, SLEN, DMODEL, DMODEL);

    dim3 agrid(SLEN / BQ, NHEAD);
    flash_attn_mma<<<agrid, ATHREADS>>>(qp, kp, vp, ap);

    gemm_tf32_nt<<<ggrid, 256>>>(ap, Wo, nullptr, out, SLEN, DMODEL, DMODEL);
}

// round 7
// speedup vs baseline: 2.6604x; 1.7915x over previous
#include <cuda_runtime.h>
#include <cuda_fp16.h>
#include <math.h>
#include <stdint.h>

#define SLEN 4096
#define DMODEL 1024
#define NHEAD 16
#define HDIM 64

// scratch (allocation-free rule: __device__ globals)
__device__ float g_q[SLEN * DMODEL];
__device__ float g_k[SLEN * DMODEL];
__device__ float g_v[SLEN * DMODEL];
__device__ float g_attn[SLEN * DMODEL];

// ---------------------------------------------------------------------------
// helpers
// ---------------------------------------------------------------------------
__device__ __forceinline__ void split2(float a, float b, uint32_t& hi, uint32_t& lo) {
    __half ha = __float2half_rn(a);
    __half hb = __float2half_rn(b);
    __half la = __float2half_rn(a - __half2float(ha));
    __half lb = __float2half_rn(b - __half2float(hb));
    __half2 h = __halves2half2(ha, hb);
    __half2 l = __halves2half2(la, lb);
    hi = *(uint32_t*)&h;
    lo = *(uint32_t*)&l;
}

__device__ __forceinline__ void mma_f16(
    float c[4], uint32_t a0, uint32_t a1, uint32_t a2, uint32_t a3,
    uint32_t b0, uint32_t b1)
{
    asm volatile(
        "mma.sync.aligned.m16n8k16.row.col.f32.f16.f16.f32 "
        "{%0,%1,%2,%3},{%4,%5,%6,%7},{%8,%9},{%0,%1,%2,%3};\n"
        : "+f"(c[0]), "+f"(c[1]), "+f"(c[2]), "+f"(c[3])
        : "r"(a0), "r"(a1), "r"(a2), "r"(a3), "r"(b0), "r"(b1));
}

// ---------------------------------------------------------------------------
// C[M][N] = A[M][K] @ B[N][K]^T + bias[N] via 3xFP16 mma (error-compensated).
// BM=BN=128, k-step 16, 256 threads (2x4 warps, warp tile 64x32).
// Double-buffered smem, one sync per k-step.
// ---------------------------------------------------------------------------
#define BM 128
#define BN 128
#define GS 12      // uint32 (half2) per row: 8 data + 4 pad (conflict-free frags)

__global__ __launch_bounds__(256) void gemm_f16x3_nt(
    const float* __restrict__ A, const float* __restrict__ B,
    const float* __restrict__ bias, float* __restrict__ C,
    int M, int N, int K)
{
    __shared__ uint32_t AsH[2][BM][GS];
    __shared__ uint32_t AsL[2][BM][GS];
    __shared__ uint32_t BsH[2][BN][GS];
    __shared__ uint32_t BsL[2][BN][GS];

    const int tid  = threadIdx.x;
    const int warp = tid >> 5;
    const int lane = tid & 31;
    const int wm = warp >> 2;
    const int wn = warp & 3;
    const int lr = lane >> 2;
    const int qd = lane & 3;
    const int brow = blockIdx.y * BM;
    const int bcol = blockIdx.x * BN;

    float acc[4][4][4];
#pragma unroll
    for (int i = 0; i < 4; i++)
#pragma unroll
        for (int j = 0; j < 4; j++)
#pragma unroll
            for (int f = 0; f < 4; f++) acc[i][j][f] = 0.f;

    const int NKB = K / 16;

    auto load_tile = [&](int kb, int buf) {
#pragma unroll
        for (int it = 0; it < 2; it++) {
            int f   = tid + it * 256;
            int row = f >> 2;
            int c4  = (f & 3) * 4;      // float col base
            int h2  = c4 >> 1;          // half2 col base
            float4 a4 = *(const float4*)&A[(size_t)(brow + row) * K + kb * 16 + c4];
            split2(a4.x, a4.y, AsH[buf][row][h2],     AsL[buf][row][h2]);
            split2(a4.z, a4.w, AsH[buf][row][h2 + 1], AsL[buf][row][h2 + 1]);
            float4 b4 = *(const float4*)&B[(size_t)(bcol + row) * K + kb * 16 + c4];
            split2(b4.x, b4.y, BsH[buf][row][h2],     BsL[buf][row][h2]);
            split2(b4.z, b4.w, BsH[buf][row][h2 + 1], BsL[buf][row][h2 + 1]);
        }
    };

    load_tile(0, 0);
    __syncthreads();

    for (int kb = 0; kb < NKB; kb++) {
        const int buf = kb & 1;
        if (kb + 1 < NKB) load_tile(kb + 1, buf ^ 1);

        uint32_t ah[4][4], al[4][4];
#pragma unroll
        for (int mt = 0; mt < 4; mt++) {
            int r = wm * 64 + mt * 16 + lr;
            ah[mt][0] = AsH[buf][r    ][qd];
            ah[mt][1] = AsH[buf][r + 8][qd];
            ah[mt][2] = AsH[buf][r    ][qd + 4];
            ah[mt][3] = AsH[buf][r + 8][qd + 4];
            al[mt][0] = AsL[buf][r    ][qd];
            al[mt][1] = AsL[buf][r + 8][qd];
            al[mt][2] = AsL[buf][r    ][qd + 4];
            al[mt][3] = AsL[buf][r + 8][qd + 4];
        }
#pragma unroll
        for (int nt = 0; nt < 4; nt++) {
            int c = wn * 32 + nt * 8 + lr;
            uint32_t bh0 = BsH[buf][c][qd], bh1 = BsH[buf][c][qd + 4];
            uint32_t bl0 = BsL[buf][c][qd], bl1 = BsL[buf][c][qd + 4];
#pragma unroll
            for (int mt = 0; mt < 4; mt++) {
                mma_f16(acc[mt][nt], ah[mt][0], ah[mt][1], ah[mt][2], ah[mt][3], bh0, bh1);
                mma_f16(acc[mt][nt], ah[mt][0], ah[mt][1], ah[mt][2], ah[mt][3], bl0, bl1);
                mma_f16(acc[mt][nt], al[mt][0], al[mt][1], al[mt][2], al[mt][3], bh0, bh1);
            }
        }
        __syncthreads();
    }

#pragma unroll
    for (int mt = 0; mt < 4; mt++) {
        int r0 = brow + wm * 64 + mt * 16 + lr;
#pragma unroll
        for (int nt = 0; nt < 4; nt++) {
            int col = bcol + wn * 32 + nt * 8 + 2 * qd;
            float b0 = bias ? bias[col]     : 0.f;
            float b1 = bias ? bias[col + 1] : 0.f;
            float2 w0 = make_float2(acc[mt][nt][0] + b0, acc[mt][nt][1] + b1);
            float2 w1 = make_float2(acc[mt][nt][2] + b0, acc[mt][nt][3] + b1);
            *(float2*)&C[(size_t)r0 * N + col]       = w0;
            *(float2*)&C[(size_t)(r0 + 8) * N + col] = w1;
        }
    }
}

// ---------------------------------------------------------------------------
// Tensor-core causal flash attention with ALiBi (all-fp16 mma).
// BQ=64 = 4 warps x m16, 128 threads, BT=32.
// S via 3xFP16 k16 mma, PV via fp16 mma (register pass-through P).
// K/V double-buffered: one sync per tile, next-tile loads issued pre-compute.
// ---------------------------------------------------------------------------
#define BQ 64
#define BT 32
#define QS 36        // uint32 per Q/K row: 32 data + 4 pad (conflict-free)
#define VPAD 8
#define ATHREADS 128

__global__ __launch_bounds__(ATHREADS) void flash_attn_f16(
    const float* __restrict__ Q, const float* __restrict__ K,
    const float* __restrict__ V, float* __restrict__ O)
{
    const int h  = blockIdx.y;
    const int qt = gridDim.x - 1 - blockIdx.x;   // longest first
    const int q0 = qt * BQ;

    const int tid  = threadIdx.x;
    const int warp = tid >> 5;
    const int lane = tid & 31;
    const int lr   = lane >> 2;
    const int qd   = lane & 3;
    const int R    = warp * 16;

    __shared__ uint32_t Qh2[BQ][QS];            // 9216 B
    __shared__ uint32_t Ql2[BQ][QS];            // 9216 B
    __shared__ uint32_t Kh2[2][BT][QS];         // 9216 B
    __shared__ uint32_t Kl2[2][BT][QS];         // 9216 B
    __shared__ __half   VsT[2][HDIM][BT + VPAD];// 10240 B   (total 47104 B)

    const float LOG2E = 1.4426950408889634f;
    const float sc2 = 0.125f * LOG2E;
    const float sl2 = exp2f(-0.5f * (float)(h + 1)) * LOG2E;

    // ---- stage Q tile (hi/lo fp16 split) ----
    for (int f = tid; f < BQ * 16; f += ATHREADS) {
        int r  = f >> 4;
        int c4 = (f & 15) * 4;
        int h2 = c4 >> 1;
        float4 v4 = *(const float4*)&Q[(size_t)(q0 + r) * DMODEL + h * HDIM + c4];
        split2(v4.x, v4.y, Qh2[r][h2],     Ql2[r][h2]);
        split2(v4.z, v4.w, Qh2[r][h2 + 1], Ql2[r][h2 + 1]);
    }

    auto load_kv = [&](int t, int buf) {
        const int t0 = t * BT;
        for (int f = tid; f < BT * 16; f += ATHREADS) {
            int tk = f >> 4;
            int c4 = (f & 15) * 4;
            int h2 = c4 >> 1;
            float4 k4 = *(const float4*)&K[(size_t)(t0 + tk) * DMODEL + h * HDIM + c4];
            split2(k4.x, k4.y, Kh2[buf][tk][h2],     Kl2[buf][tk][h2]);
            split2(k4.z, k4.w, Kh2[buf][tk][h2 + 1], Kl2[buf][tk][h2 + 1]);
        }
        for (int f = tid; f < HDIM * (BT / 2); f += ATHREADS) {
            int dv = f & 63;
            int tp = f >> 6;
            const float* vp = &V[(size_t)(t0 + 2 * tp) * DMODEL + h * HDIM + dv];
            float va = vp[0];
            float vb = vp[DMODEL];
            *(__half2*)&VsT[buf][dv][2 * tp] = __floats2half2_rn(va, vb);
        }
    };

    load_kv(0, 0);
    __syncthreads();

    // ---- Q fragments (hi and lo) in registers ----
    uint32_t qh[4][4], ql[4][4];
#pragma unroll
    for (int kt = 0; kt < 4; kt++) {
        int c0 = kt * 8 + qd;
        qh[kt][0] = Qh2[R + lr    ][c0];
        qh[kt][1] = Qh2[R + lr + 8][c0];
        qh[kt][2] = Qh2[R + lr    ][c0 + 4];
        qh[kt][3] = Qh2[R + lr + 8][c0 + 4];
        ql[kt][0] = Ql2[R + lr    ][c0];
        ql[kt][1] = Ql2[R + lr + 8][c0];
        ql[kt][2] = Ql2[R + lr    ][c0 + 4];
        ql[kt][3] = Ql2[R + lr + 8][c0 + 4];
    }

    float oacc[8][4];
#pragma unroll
    for (int i = 0; i < 8; i++)
#pragma unroll
        for (int j = 0; j < 4; j++) oacc[i][j] = 0.f;
    float m0 = -INFINITY, m1 = -INFINITY, l0 = 0.f, l1 = 0.f;

    const int gr0 = q0 + R + lr;
    const int gr1 = gr0 + 8;

    const int ntiles = 2 * (qt + 1);
    for (int t = 0; t < ntiles; t++) {
        const int buf = t & 1;
        const int t0 = t * BT;
        if (t + 1 < ntiles) load_kv(t + 1, buf ^ 1);

        // ---- S = Q K^T (3xFP16, k16) ----
        float sa[4][4];
#pragma unroll
        for (int nt = 0; nt < 4; nt++)
#pragma unroll
            for (int f = 0; f < 4; f++) sa[nt][f] = 0.f;

#pragma unroll
        for (int kt = 0; kt < 4; kt++) {
            int c0 = kt * 8 + qd;
#pragma unroll
            for (int nt = 0; nt < 4; nt++) {
                int tr_ = nt * 8 + lr;
                uint32_t bh0 = Kh2[buf][tr_][c0], bh1 = Kh2[buf][tr_][c0 + 4];
                uint32_t bl0 = Kl2[buf][tr_][c0], bl1 = Kl2[buf][tr_][c0 + 4];
                mma_f16(sa[nt], qh[kt][0], qh[kt][1], qh[kt][2], qh[kt][3], bh0, bh1);
                mma_f16(sa[nt], qh[kt][0], qh[kt][1], qh[kt][2], qh[kt][3], bl0, bl1);
                mma_f16(sa[nt], ql[kt][0], ql[kt][1], ql[kt][2], ql[kt][3], bh0, bh1);
            }
        }

        // ---- bias + causal mask + online softmax (base-2) ----
        float mx0 = -INFINITY, mx1 = -INFINITY;
#pragma unroll
        for (int nt = 0; nt < 4; nt++) {
            int c = t0 + nt * 8 + 2 * qd;
            float x00 = sa[nt][0] * sc2 - sl2 * (float)c;
            float x01 = sa[nt][1] * sc2 - sl2 * (float)(c + 1);
            float x10 = sa[nt][2] * sc2 - sl2 * (float)c;
            float x11 = sa[nt][3] * sc2 - sl2 * (float)(c + 1);
            if (c     > gr0) x00 = -INFINITY;
            if (c + 1 > gr0) x01 = -INFINITY;
            if (c     > gr1) x10 = -INFINITY;
            if (c + 1 > gr1) x11 = -INFINITY;
            sa[nt][0] = x00; sa[nt][1] = x01; sa[nt][2] = x10; sa[nt][3] = x11;
            mx0 = fmaxf(mx0, fmaxf(x00, x01));
            mx1 = fmaxf(mx1, fmaxf(x10, x11));
        }
        mx0 = fmaxf(mx0, __shfl_xor_sync(0xffffffffu, mx0, 1));
        mx0 = fmaxf(mx0, __shfl_xor_sync(0xffffffffu, mx0, 2));
        mx1 = fmaxf(mx1, __shfl_xor_sync(0xffffffffu, mx1, 1));
        mx1 = fmaxf(mx1, __shfl_xor_sync(0xffffffffu, mx1, 2));

        float nm0 = fmaxf(m0, mx0), nm1 = fmaxf(m1, mx1);
        float s0 = exp2f(m0 - nm0), s1 = exp2f(m1 - nm1);
        m0 = nm0; m1 = nm1;

        float rs0 = 0.f, rs1 = 0.f;
        uint32_t pa[2][4];
#pragma unroll
        for (int nt = 0; nt < 4; nt++) {
            float p00 = exp2f(sa[nt][0] - m0);
            float p01 = exp2f(sa[nt][1] - m0);
            float p10 = exp2f(sa[nt][2] - m1);
            float p11 = exp2f(sa[nt][3] - m1);
            rs0 += p00 + p01;
            rs1 += p10 + p11;
            __half2 h0 = __floats2half2_rn(p00, p01);
            __half2 h1 = __floats2half2_rn(p10, p11);
            pa[nt >> 1][(nt & 1) * 2 + 0] = *(uint32_t*)&h0;
            pa[nt >> 1][(nt & 1) * 2 + 1] = *(uint32_t*)&h1;
        }
        rs0 += __shfl_xor_sync(0xffffffffu, rs0, 1);
        rs0 += __shfl_xor_sync(0xffffffffu, rs0, 2);
        rs1 += __shfl_xor_sync(0xffffffffu, rs1, 1);
        rs1 += __shfl_xor_sync(0xffffffffu, rs1, 2);
        l0 = l0 * s0 + rs0;
        l1 = l1 * s1 + rs1;

        // ---- rescale O, then O += P V (fp16 mma) ----
#pragma unroll
        for (int ntO = 0; ntO < 8; ntO++) {
            oacc[ntO][0] *= s0; oacc[ntO][1] *= s0;
            oacc[ntO][2] *= s1; oacc[ntO][3] *= s1;
        }
#pragma unroll
        for (int ktp = 0; ktp < 2; ktp++) {
#pragma unroll
            for (int ntO = 0; ntO < 8; ntO++) {
                int dcol = ntO * 8 + lr;
                uint32_t b0 = *(const uint32_t*)&VsT[buf][dcol][ktp * 16 + 2 * qd];
                uint32_t b1 = *(const uint32_t*)&VsT[buf][dcol][ktp * 16 + 2 * qd + 8];
                mma_f16(oacc[ntO], pa[ktp][0], pa[ktp][1], pa[ktp][2], pa[ktp][3], b0, b1);
            }
        }
        __syncthreads();
    }

    // ---- epilogue ----
    float inv0 = 1.f / l0, inv1 = 1.f / l1;
#pragma unroll
    for (int ntO = 0; ntO < 8; ntO++) {
        int col = h * HDIM + ntO * 8 + 2 * qd;
        float2 w0 = make_float2(oacc[ntO][0] * inv0, oacc[ntO][1] * inv0);
        float2 w1 = make_float2(oacc[ntO][2] * inv1, oacc[ntO][3] * inv1);
        *(float2*)&O[(size_t)gr0 * DMODEL + col] = w0;
        *(float2*)&O[(size_t)gr1 * DMODEL + col] = w1;
    }
}

// ---------------------------------------------------------------------------
extern "C" void kernel_launch(void* const* d_in, const int* in_sizes, int n_in,
                              void* d_out, int out_size)
{
    const float* x  = (const float*)d_in[0];
    const float* Wq = (const float*)d_in[1];
    const float* bq = (const float*)d_in[2];
    const float* Wk = (const float*)d_in[3];
    const float* Wv = (const float*)d_in[4];
    const float* bv = (const float*)d_in[5];
    const float* Wo = (const float*)d_in[6];
    float* out = (float*)d_out;

    float *qp, *kp, *vp, *ap;
    cudaGetSymbolAddress((void**)&qp, g_q);
    cudaGetSymbolAddress((void**)&kp, g_k);
    cudaGetSymbolAddress((void**)&vp, g_v);
    cudaGetSymbolAddress((void**)&ap, g_attn);

    dim3 ggrid(DMODEL / BN, SLEN / BM);
    gemm_f16x3_nt<<<ggrid, 256>>>(x, Wq, bq, qp, SLEN, DMODEL, DMODEL);
    gemm_f16x3_nt<<<ggrid, 256>>>(x, Wk, nullptr, kp, SLEN, DMODEL, DMODEL);
    gemm_f16x3_nt<<<ggrid, 256>>>(x, Wv, bv, vp, SLEN, DMODEL, DMODEL);

    dim3 agrid(SLEN / BQ, NHEAD);
    flash_attn_f16<<<agrid, ATHREADS>>>(qp, kp, vp, ap);

    gemm_f16x3_nt<<<ggrid, 256>>>(ap, Wo, nullptr, out, SLEN, DMODEL, DMODEL);
}

// round 8
// speedup vs baseline: 3.1480x; 1.1833x over previous
#include <cuda_runtime.h>
#include <cuda_fp16.h>
#include <math.h>
#include <stdint.h>

#define SLEN 4096
#define DMODEL 1024
#define NHEAD 16
#define HDIM 64

// scratch (allocation-free rule: __device__ globals)
__device__ float g_q[SLEN * DMODEL];
__device__ float g_k[SLEN * DMODEL];
__device__ float g_v[SLEN * DMODEL];
__device__ float g_attn[SLEN * DMODEL];

// ---------------------------------------------------------------------------
// helpers
// ---------------------------------------------------------------------------
__device__ __forceinline__ void split2(float a, float b, uint32_t& hi, uint32_t& lo) {
    __half ha = __float2half_rn(a);
    __half hb = __float2half_rn(b);
    __half la = __float2half_rn(a - __half2float(ha));
    __half lb = __float2half_rn(b - __half2float(hb));
    __half2 h = __halves2half2(ha, hb);
    __half2 l = __halves2half2(la, lb);
    hi = *(uint32_t*)&h;
    lo = *(uint32_t*)&l;
}

__device__ __forceinline__ void mma_f16(
    float c[4], uint32_t a0, uint32_t a1, uint32_t a2, uint32_t a3,
    uint32_t b0, uint32_t b1)
{
    asm volatile(
        "mma.sync.aligned.m16n8k16.row.col.f32.f16.f16.f32 "
        "{%0,%1,%2,%3},{%4,%5,%6,%7},{%8,%9},{%0,%1,%2,%3};\n"
        : "+f"(c[0]), "+f"(c[1]), "+f"(c[2]), "+f"(c[3])
        : "r"(a0), "r"(a1), "r"(a2), "r"(a3), "r"(b0), "r"(b1));
}

// ---------------------------------------------------------------------------
// C[M][N] = A[M][K] @ B[N][K]^T + bias[N] via 3xFP16 mma (error-compensated).
// ---------------------------------------------------------------------------
#define BM 128
#define BN 128
#define GS 12

__global__ __launch_bounds__(256) void gemm_f16x3_nt(
    const float* __restrict__ A, const float* __restrict__ B,
    const float* __restrict__ bias, float* __restrict__ C,
    int M, int N, int K)
{
    __shared__ uint32_t AsH[2][BM][GS];
    __shared__ uint32_t AsL[2][BM][GS];
    __shared__ uint32_t BsH[2][BN][GS];
    __shared__ uint32_t BsL[2][BN][GS];

    const int tid  = threadIdx.x;
    const int warp = tid >> 5;
    const int lane = tid & 31;
    const int wm = warp >> 2;
    const int wn = warp & 3;
    const int lr = lane >> 2;
    const int qd = lane & 3;
    const int brow = blockIdx.y * BM;
    const int bcol = blockIdx.x * BN;

    float acc[4][4][4];
#pragma unroll
    for (int i = 0; i < 4; i++)
#pragma unroll
        for (int j = 0; j < 4; j++)
#pragma unroll
            for (int f = 0; f < 4; f++) acc[i][j][f] = 0.f;

    const int NKB = K / 16;

    auto load_tile = [&](int kb, int buf) {
#pragma unroll
        for (int it = 0; it < 2; it++) {
            int f   = tid + it * 256;
            int row = f >> 2;
            int c4  = (f & 3) * 4;
            int h2  = c4 >> 1;
            float4 a4 = *(const float4*)&A[(size_t)(brow + row) * K + kb * 16 + c4];
            split2(a4.x, a4.y, AsH[buf][row][h2],     AsL[buf][row][h2]);
            split2(a4.z, a4.w, AsH[buf][row][h2 + 1], AsL[buf][row][h2 + 1]);
            float4 b4 = *(const float4*)&B[(size_t)(bcol + row) * K + kb * 16 + c4];
            split2(b4.x, b4.y, BsH[buf][row][h2],     BsL[buf][row][h2]);
            split2(b4.z, b4.w, BsH[buf][row][h2 + 1], BsL[buf][row][h2 + 1]);
        }
    };

    load_tile(0, 0);
    __syncthreads();

    for (int kb = 0; kb < NKB; kb++) {
        const int buf = kb & 1;
        if (kb + 1 < NKB) load_tile(kb + 1, buf ^ 1);

        uint32_t ah[4][4], al[4][4];
#pragma unroll
        for (int mt = 0; mt < 4; mt++) {
            int r = wm * 64 + mt * 16 + lr;
            ah[mt][0] = AsH[buf][r    ][qd];
            ah[mt][1] = AsH[buf][r + 8][qd];
            ah[mt][2] = AsH[buf][r    ][qd + 4];
            ah[mt][3] = AsH[buf][r + 8][qd + 4];
            al[mt][0] = AsL[buf][r    ][qd];
            al[mt][1] = AsL[buf][r + 8][qd];
            al[mt][2] = AsL[buf][r    ][qd + 4];
            al[mt][3] = AsL[buf][r + 8][qd + 4];
        }
#pragma unroll
        for (int nt = 0; nt < 4; nt++) {
            int c = wn * 32 + nt * 8 + lr;
            uint32_t bh0 = BsH[buf][c][qd], bh1 = BsH[buf][c][qd + 4];
            uint32_t bl0 = BsL[buf][c][qd], bl1 = BsL[buf][c][qd + 4];
#pragma unroll
            for (int mt = 0; mt < 4; mt++) {
                mma_f16(acc[mt][nt], ah[mt][0], ah[mt][1], ah[mt][2], ah[mt][3], bh0, bh1);
                mma_f16(acc[mt][nt], ah[mt][0], ah[mt][1], ah[mt][2], ah[mt][3], bl0, bl1);
                mma_f16(acc[mt][nt], al[mt][0], al[mt][1], al[mt][2], al[mt][3], bh0, bh1);
            }
        }
        __syncthreads();
    }

#pragma unroll
    for (int mt = 0; mt < 4; mt++) {
        int r0 = brow + wm * 64 + mt * 16 + lr;
#pragma unroll
        for (int nt = 0; nt < 4; nt++) {
            int col = bcol + wn * 32 + nt * 8 + 2 * qd;
            float b0 = bias ? bias[col]     : 0.f;
            float b1 = bias ? bias[col + 1] : 0.f;
            float2 w0 = make_float2(acc[mt][nt][0] + b0, acc[mt][nt][1] + b1);
            float2 w1 = make_float2(acc[mt][nt][2] + b0, acc[mt][nt][3] + b1);
            *(float2*)&C[(size_t)r0 * N + col]       = w0;
            *(float2*)&C[(size_t)(r0 + 8) * N + col] = w1;
        }
    }
}

// ---------------------------------------------------------------------------
// Tensor-core causal flash attention with ALiBi (all-fp16 mma).
// BALANCED: each CTA processes complementary q-tiles (bx, 63-bx) -> every
// CTA does exactly 130 key-tiles. Grid 32x16 = 512 CTAs = one wave.
// ---------------------------------------------------------------------------
#define BQ 64
#define BT 32
#define QS 36
#define VPAD 8
#define ATHREADS 128
#define NQT (SLEN / BQ)       // 64

__global__ __launch_bounds__(ATHREADS) void flash_attn_f16(
    const float* __restrict__ Q, const float* __restrict__ K,
    const float* __restrict__ V, float* __restrict__ O)
{
    const int h = blockIdx.y;

    const int tid  = threadIdx.x;
    const int warp = tid >> 5;
    const int lane = tid & 31;
    const int lr   = lane >> 2;
    const int qd   = lane & 3;
    const int R    = warp * 16;

    __shared__ uint32_t Qh2[BQ][QS];
    __shared__ uint32_t Ql2[BQ][QS];
    __shared__ uint32_t Kh2[2][BT][QS];
    __shared__ uint32_t Kl2[2][BT][QS];
    __shared__ __half   VsT[2][HDIM][BT + VPAD];

    const float LOG2E = 1.4426950408889634f;
    const float sc2 = 0.125f * LOG2E;
    const float sl2 = exp2f(-0.5f * (float)(h + 1)) * LOG2E;

    auto load_kv = [&](int t, int buf) {
        const int t0 = t * BT;
        for (int f = tid; f < BT * 16; f += ATHREADS) {
            int tk = f >> 4;
            int c4 = (f & 15) * 4;
            int h2 = c4 >> 1;
            float4 k4 = *(const float4*)&K[(size_t)(t0 + tk) * DMODEL + h * HDIM + c4];
            split2(k4.x, k4.y, Kh2[buf][tk][h2],     Kl2[buf][tk][h2]);
            split2(k4.z, k4.w, Kh2[buf][tk][h2 + 1], Kl2[buf][tk][h2 + 1]);
        }
        for (int f = tid; f < HDIM * (BT / 2); f += ATHREADS) {
            int dv = f & 63;
            int tp = f >> 6;
            const float* vp = &V[(size_t)(t0 + 2 * tp) * DMODEL + h * HDIM + dv];
            float va = vp[0];
            float vb = vp[DMODEL];
            *(__half2*)&VsT[buf][dv][2 * tp] = __floats2half2_rn(va, vb);
        }
    };

#pragma unroll 1
    for (int rep = 0; rep < 2; rep++) {
        const int qt = (rep == 0) ? (int)blockIdx.x : (NQT - 1 - (int)blockIdx.x);
        const int q0 = qt * BQ;

        // ---- stage Q tile (hi/lo fp16 split) ----
        // trailing sync of previous rep (or none needed on rep 0) protects reuse
        for (int f = tid; f < BQ * 16; f += ATHREADS) {
            int r  = f >> 4;
            int c4 = (f & 15) * 4;
            int h2 = c4 >> 1;
            float4 v4 = *(const float4*)&Q[(size_t)(q0 + r) * DMODEL + h * HDIM + c4];
            split2(v4.x, v4.y, Qh2[r][h2],     Ql2[r][h2]);
            split2(v4.z, v4.w, Qh2[r][h2 + 1], Ql2[r][h2 + 1]);
        }
        load_kv(0, 0);
        __syncthreads();

        // ---- Q fragments (hi and lo) in registers ----
        uint32_t qh[4][4], ql[4][4];
#pragma unroll
        for (int kt = 0; kt < 4; kt++) {
            int c0 = kt * 8 + qd;
            qh[kt][0] = Qh2[R + lr    ][c0];
            qh[kt][1] = Qh2[R + lr + 8][c0];
            qh[kt][2] = Qh2[R + lr    ][c0 + 4];
            qh[kt][3] = Qh2[R + lr + 8][c0 + 4];
            ql[kt][0] = Ql2[R + lr    ][c0];
            ql[kt][1] = Ql2[R + lr + 8][c0];
            ql[kt][2] = Ql2[R + lr    ][c0 + 4];
            ql[kt][3] = Ql2[R + lr + 8][c0 + 4];
        }

        float oacc[8][4];
#pragma unroll
        for (int i = 0; i < 8; i++)
#pragma unroll
            for (int j = 0; j < 4; j++) oacc[i][j] = 0.f;
        float m0 = -INFINITY, m1 = -INFINITY, l0 = 0.f, l1 = 0.f;

        const int gr0 = q0 + R + lr;
        const int gr1 = gr0 + 8;

        const int ntiles = 2 * (qt + 1);
        for (int t = 0; t < ntiles; t++) {
            const int buf = t & 1;
            const int t0 = t * BT;
            if (t + 1 < ntiles) load_kv(t + 1, buf ^ 1);

            // ---- S = Q K^T (3xFP16, k16) ----
            float sa[4][4];
#pragma unroll
            for (int nt = 0; nt < 4; nt++)
#pragma unroll
                for (int f = 0; f < 4; f++) sa[nt][f] = 0.f;

#pragma unroll
            for (int kt = 0; kt < 4; kt++) {
                int c0 = kt * 8 + qd;
#pragma unroll
                for (int nt = 0; nt < 4; nt++) {
                    int tr_ = nt * 8 + lr;
                    uint32_t bh0 = Kh2[buf][tr_][c0], bh1 = Kh2[buf][tr_][c0 + 4];
                    uint32_t bl0 = Kl2[buf][tr_][c0], bl1 = Kl2[buf][tr_][c0 + 4];
                    mma_f16(sa[nt], qh[kt][0], qh[kt][1], qh[kt][2], qh[kt][3], bh0, bh1);
                    mma_f16(sa[nt], qh[kt][0], qh[kt][1], qh[kt][2], qh[kt][3], bl0, bl1);
                    mma_f16(sa[nt], ql[kt][0], ql[kt][1], ql[kt][2], ql[kt][3], bh0, bh1);
                }
            }

            // ---- bias + causal mask + online softmax (base-2) ----
            float mx0 = -INFINITY, mx1 = -INFINITY;
#pragma unroll
            for (int nt = 0; nt < 4; nt++) {
                int c = t0 + nt * 8 + 2 * qd;
                float x00 = sa[nt][0] * sc2 - sl2 * (float)c;
                float x01 = sa[nt][1] * sc2 - sl2 * (float)(c + 1);
                float x10 = sa[nt][2] * sc2 - sl2 * (float)c;
                float x11 = sa[nt][3] * sc2 - sl2 * (float)(c + 1);
                if (c     > gr0) x00 = -INFINITY;
                if (c + 1 > gr0) x01 = -INFINITY;
                if (c     > gr1) x10 = -INFINITY;
                if (c + 1 > gr1) x11 = -INFINITY;
                sa[nt][0] = x00; sa[nt][1] = x01; sa[nt][2] = x10; sa[nt][3] = x11;
                mx0 = fmaxf(mx0, fmaxf(x00, x01));
                mx1 = fmaxf(mx1, fmaxf(x10, x11));
            }
            mx0 = fmaxf(mx0, __shfl_xor_sync(0xffffffffu, mx0, 1));
            mx0 = fmaxf(mx0, __shfl_xor_sync(0xffffffffu, mx0, 2));
            mx1 = fmaxf(mx1, __shfl_xor_sync(0xffffffffu, mx1, 1));
            mx1 = fmaxf(mx1, __shfl_xor_sync(0xffffffffu, mx1, 2));

            float nm0 = fmaxf(m0, mx0), nm1 = fmaxf(m1, mx1);
            float s0 = exp2f(m0 - nm0), s1 = exp2f(m1 - nm1);
            m0 = nm0; m1 = nm1;

            float rs0 = 0.f, rs1 = 0.f;
            uint32_t pa[2][4];
#pragma unroll
            for (int nt = 0; nt < 4; nt++) {
                float p00 = exp2f(sa[nt][0] - m0);
                float p01 = exp2f(sa[nt][1] - m0);
                float p10 = exp2f(sa[nt][2] - m1);
                float p11 = exp2f(sa[nt][3] - m1);
                rs0 += p00 + p01;
                rs1 += p10 + p11;
                __half2 h0 = __floats2half2_rn(p00, p01);
                __half2 h1 = __floats2half2_rn(p10, p11);
                pa[nt >> 1][(nt & 1) * 2 + 0] = *(uint32_t*)&h0;
                pa[nt >> 1][(nt & 1) * 2 + 1] = *(uint32_t*)&h1;
            }
            rs0 += __shfl_xor_sync(0xffffffffu, rs0, 1);
            rs0 += __shfl_xor_sync(0xffffffffu, rs0, 2);
            rs1 += __shfl_xor_sync(0xffffffffu, rs1, 1);
            rs1 += __shfl_xor_sync(0xffffffffu, rs1, 2);
            l0 = l0 * s0 + rs0;
            l1 = l1 * s1 + rs1;

            // ---- rescale O, then O += P V (fp16 mma) ----
#pragma unroll
            for (int ntO = 0; ntO < 8; ntO++) {
                oacc[ntO][0] *= s0; oacc[ntO][1] *= s0;
                oacc[ntO][2] *= s1; oacc[ntO][3] *= s1;
            }
#pragma unroll
            for (int ktp = 0; ktp < 2; ktp++) {
#pragma unroll
                for (int ntO = 0; ntO < 8; ntO++) {
                    int dcol = ntO * 8 + lr;
                    uint32_t b0 = *(const uint32_t*)&VsT[buf][dcol][ktp * 16 + 2 * qd];
                    uint32_t b1 = *(const uint32_t*)&VsT[buf][dcol][ktp * 16 + 2 * qd + 8];
                    mma_f16(oacc[ntO], pa[ktp][0], pa[ktp][1], pa[ktp][2], pa[ktp][3], b0, b1);
                }
            }
            __syncthreads();
        }

        // ---- epilogue ----
        float inv0 = 1.f / l0, inv1 = 1.f / l1;
#pragma unroll
        for (int ntO = 0; ntO < 8; ntO++) {
            int col = h * HDIM + ntO * 8 + 2 * qd;
            float2 w0 = make_float2(oacc[ntO][0] * inv0, oacc[ntO][1] * inv0);
            float2 w1 = make_float2(oacc[ntO][2] * inv1, oacc[ntO][3] * inv1);
            *(float2*)&O[(size_t)gr0 * DMODEL + col] = w0;
            *(float2*)&O[(size_t)gr1 * DMODEL + col] = w1;
        }
    }
}

// ---------------------------------------------------------------------------
extern "C" void kernel_launch(void* const* d_in, const int* in_sizes, int n_in,
                              void* d_out, int out_size)
{
    const float* x  = (const float*)d_in[0];
    const float* Wq = (const float*)d_in[1];
    const float* bq = (const float*)d_in[2];
    const float* Wk = (const float*)d_in[3];
    const float* Wv = (const float*)d_in[4];
    const float* bv = (const float*)d_in[5];
    const float* Wo = (const float*)d_in[6];
    float* out = (float*)d_out;

    float *qp, *kp, *vp, *ap;
    cudaGetSymbolAddress((void**)&qp, g_q);
    cudaGetSymbolAddress((void**)&kp, g_k);
    cudaGetSymbolAddress((void**)&vp, g_v);
    cudaGetSymbolAddress((void**)&ap, g_attn);

    dim3 ggrid(DMODEL / BN, SLEN / BM);
    gemm_f16x3_nt<<<ggrid, 256>>>(x, Wq, bq, qp, SLEN, DMODEL, DMODEL);
    gemm_f16x3_nt<<<ggrid, 256>>>(x, Wk, nullptr, kp, SLEN, DMODEL, DMODEL);
    gemm_f16x3_nt<<<ggrid, 256>>>(x, Wv, bv, vp, SLEN, DMODEL, DMODEL);

    dim3 agrid(NQT / 2, NHEAD);   // (32, 16) balanced pairs
    flash_attn_f16<<<agrid, ATHREADS>>>(qp, kp, vp, ap);

    gemm_f16x3_nt<<<ggrid, 256>>>(ap, Wo, nullptr, out, SLEN, DMODEL, DMODEL);
}